// round 11
// baseline (speedup 1.0000x reference)
#include <cuda_runtime.h>
#include <cuda_bf16.h>
#include <math.h>

#define B_SZ 256
#define R_SZ 2048
#define D_SZ 64
#define K_TOP 20
#define BLOCKS_PER_B 64          /* 32 rows per block */

// Candidate state. Zero-initialized at load; the finisher block re-zeros
// g_cnt/g_done after consuming them, so every launch/replay starts clean.
__device__ int                g_cnt[B_SZ];
__device__ int                g_done[B_SZ];
__device__ unsigned long long g_cand[B_SZ * R_SZ];
__device__ float              g_rinv[B_SZ * R_SZ];

__device__ __forceinline__ unsigned packf(float f) {
    unsigned u = __float_as_uint(f);
    return (u & 0x80000000u) ? ~u : (u | 0x80000000u);
}
__device__ __forceinline__ float unpackf(unsigned p) {
    unsigned b = (p & 0x80000000u) ? (p ^ 0x80000000u) : ~p;
    return __uint_as_float(b);
}

// ---------------------------------------------------------------------------
// Single fused kernel. Phase 1 (all blocks): stream-copy 32 rows + cosine
// sims + threshold filter (candidates published via L2 atomics). Phase 2
// (last arriving block per batch): top-k + weighting + query-row rewrite.
// ---------------------------------------------------------------------------
__global__ __launch_bounds__(256) void fused_kernel(
    const float* __restrict__ x,
    const int*   __restrict__ qrels,
    const float* __restrict__ thr_raw_p,
    const float* __restrict__ str_raw_p,
    const float* __restrict__ wscale_p,
    const float* __restrict__ temp_p,
    float*       __restrict__ out)
{
    const int tid  = threadIdx.x;
    const int wid  = tid >> 5;
    const int lane = tid & 31;
    const int half = lane >> 4;
    const int hl   = lane & 15;

    const int b = blockIdx.x >> 6;                     // 64 blocks per batch
    const long long base = (long long)blockIdx.x * 32 + wid * 4;
    const long long rowA = base + half * 2;
    const long long rowB = rowA + 1;
    const int qr = __ldg(&qrels[b]);

    // ---- phase 1: stream + sims ------------------------------------------
    const float4 vA = __ldcs(reinterpret_cast<const float4*>(x + rowA * D_SZ) + hl);
    const float4 vB = __ldcs(reinterpret_cast<const float4*>(x + rowB * D_SZ) + hl);
    const long long qrow = ((long long)b * R_SZ + qr) * D_SZ;
    const float4 q = __ldg(reinterpret_cast<const float4*>(x + qrow) + hl);

    __stcs(reinterpret_cast<float4*>(out + rowA * D_SZ) + hl, vA);
    __stcs(reinterpret_cast<float4*>(out + rowB * D_SZ) + hl, vB);

    float dotA = vA.x * q.x + vA.y * q.y + vA.z * q.z + vA.w * q.w;
    float ssA  = vA.x * vA.x + vA.y * vA.y + vA.z * vA.z + vA.w * vA.w;
    float dotB = vB.x * q.x + vB.y * q.y + vB.z * q.z + vB.w * q.w;
    float ssB  = vB.x * vB.x + vB.y * vB.y + vB.z * vB.z + vB.w * vB.w;
    float qs   = q.x * q.x + q.y * q.y + q.z * q.z + q.w * q.w;

    #pragma unroll
    for (int o = 8; o; o >>= 1) {       // stays within each 16-lane half
        dotA += __shfl_xor_sync(0xffffffffu, dotA, o);
        ssA  += __shfl_xor_sync(0xffffffffu, ssA,  o);
        dotB += __shfl_xor_sync(0xffffffffu, dotB, o);
        ssB  += __shfl_xor_sync(0xffffffffu, ssB,  o);
        qs   += __shfl_xor_sync(0xffffffffu, qs,   o);
    }

    if (hl == 0) {
        const float nqi = 1.0f / fmaxf(sqrtf(qs), 1e-12f);
        const float thr = 1.0f / (1.0f + expf(-__ldg(thr_raw_p)));
        const int rA = (int)(rowA & (R_SZ - 1));
        const int rB = rA + 1;

        const float nrA = fmaxf(sqrtf(ssA), 1e-12f);
        const float sA  = dotA * nqi / nrA;
        if (rA != qr && sA > thr) {
            const int pos = atomicAdd(&g_cnt[b], 1);
            const long long o = (long long)b * R_SZ + pos;
            atomicExch(&g_cand[o], ((unsigned long long)packf(sA) << 32)
                                   | (unsigned)(R_SZ - 1 - rA));
            atomicExch(&g_rinv[o], 1.0f / nrA);
        }
        const float nrB = fmaxf(sqrtf(ssB), 1e-12f);
        const float sB  = dotB * nqi / nrB;
        if (rB != qr && sB > thr) {
            const int pos = atomicAdd(&g_cnt[b], 1);
            const long long o = (long long)b * R_SZ + pos;
            atomicExch(&g_cand[o], ((unsigned long long)packf(sB) << 32)
                                   | (unsigned)(R_SZ - 1 - rB));
            atomicExch(&g_rinv[o], 1.0f / nrB);
        }
    }
    __syncthreads();

    // ---- arrival: last block of this batch becomes the finisher -----------
    __shared__ int s_finish;
    if (tid == 0) {
        __threadfence();                 // single release fence per block
        const int prev = atomicAdd(&g_done[b], 1);
        s_finish = (prev == BLOCKS_PER_B - 1);
    }
    __syncthreads();
    if (!s_finish) return;
    if (tid == 0) __threadfence();       // acquire side
    __syncthreads();

    // ---- phase 2: enhance for batch b --------------------------------------
    __shared__ float topv[K_TOP];
    __shared__ int   topi[K_TOP];
    __shared__ int   spos[K_TOP];
    __shared__ float srin[K_TOP];
    __shared__ float adj[K_TOP];
    __shared__ float s_strength;
    __shared__ int   s_nsel;

    const unsigned long long* cb = g_cand + (long long)b * R_SZ;

    if (tid < 32) {
        int c = 0;
        if (lane == 0) { c = g_cnt[b]; g_cnt[b] = 0; g_done[b] = 0; }
        unsigned long long k0 = __ldcg(cb + lane);
        unsigned long long k1 = __ldcg(cb + lane + 32);
        unsigned long long k2 = __ldcg(cb + lane + 64);
        unsigned long long k3 = __ldcg(cb + lane + 96);
        const int ncand = min(__shfl_sync(0xffffffffu, c, 0), R_SZ - 1);
        const int nsel  = min(ncand, K_TOP);
        if (lane == 0) s_nsel = nsel;

        if ((lane)      >= ncand) k0 = 0ull;
        if ((lane + 32) >= ncand) k1 = 0ull;
        if ((lane + 64) >= ncand) k2 = 0ull;
        if ((lane + 96) >= ncand) k3 = 0ull;

        unsigned long long prevk = ~0ull;
        for (int it = 0; it < nsel; ++it) {
            unsigned long long lb = 0ull; int lp = -1;
            if (k0 < prevk && k0 > lb) { lb = k0; lp = lane; }
            if (k1 < prevk && k1 > lb) { lb = k1; lp = lane + 32; }
            if (k2 < prevk && k2 > lb) { lb = k2; lp = lane + 64; }
            if (k3 < prevk && k3 > lb) { lb = k3; lp = lane + 96; }
            for (int j = 128 + lane; j < ncand; j += 32) {   // cold path
                unsigned long long k = __ldcg(cb + j);
                if (k < prevk && k > lb) { lb = k; lp = j; }
            }
            #pragma unroll
            for (int o = 16; o; o >>= 1) {
                unsigned long long ok = __shfl_xor_sync(0xffffffffu, lb, o);
                int op = __shfl_xor_sync(0xffffffffu, lp, o);
                if (ok > lb) { lb = ok; lp = op; }
            }
            prevk = lb;
            if (lane == 0) {
                topi[it] = (R_SZ - 1) - (int)(lb & 0xffffffffu);
                topv[it] = unpackf((unsigned)(lb >> 32));
                spos[it] = lp;
            }
        }
    }
    __syncthreads();

    const int nsel = s_nsel;
    if (tid < nsel) srin[tid] = __ldcg(g_rinv + (long long)b * R_SZ + spos[tid]);

    if (tid == 0) {
        const float thr      = 1.0f / (1.0f + expf(-thr_raw_p[0]));
        const float strength = 0.2f / (1.0f + expf(-str_raw_p[0]));
        const float tempv    = fminf(fmaxf(temp_p[0], 0.1f), 10.0f);
        const float ws       = wscale_p[0];

        float m = -1e9f;
        for (int k = 0; k < nsel; ++k) m = fmaxf(m, topv[k] / tempv);
        float se = 0.0f;
        float ev[K_TOP];
        for (int k = 0; k < nsel; ++k) { ev[k] = expf(topv[k] / tempv - m); se += ev[k]; }

        float suma = 0.0f;
        for (int k = 0; k < nsel; ++k) {
            const float wgt = ev[k] / se;
            const float sw  = 1.0f / (1.0f + expf(-(topv[k] - thr) * 10.0f));
            const float a   = wgt * sw * (1.0f + ws * topv[k]);
            adj[k] = a;
            suma  += a;
        }
        const float inv = 1.0f / (suma + 1e-8f);
        for (int k = 0; k < nsel; ++k) adj[k] *= inv;
        s_strength = strength;
    }
    __syncthreads();

    if (tid < D_SZ) {
        const long long qoff = ((long long)b * R_SZ + qr) * D_SZ;
        const float qo = x[qoff + tid];
        float acc = 0.0f;
        for (int k = 0; k < nsel; ++k)
            acc += (adj[k] * srin[k]) * x[((long long)b * R_SZ + topi[k]) * D_SZ + tid];
        const float s = s_strength;
        out[qoff + tid] = (nsel > 0) ? (1.0f - s) * qo + s * acc : qo;
    }
}

// ---------------------------------------------------------------------------
extern "C" void kernel_launch(void* const* d_in, const int* in_sizes, int n_in,
                              void* d_out, int out_size)
{
    const float* x     = (const float*)d_in[0];
    const int*   qrels = (const int*)  d_in[1];
    const float* thr   = (const float*)d_in[2];
    const float* str   = (const float*)d_in[3];
    const float* wsc   = (const float*)d_in[4];
    const float* tmp   = (const float*)d_in[5];
    float* out = (float*)d_out;

    const int blocks = B_SZ * BLOCKS_PER_B;              // 16384
    fused_kernel<<<blocks, 256>>>(x, qrels, thr, str, wsc, tmp, out);
}

// round 12
// speedup vs baseline: 1.0106x; 1.0106x over previous
#include <cuda_runtime.h>
#include <cuda_bf16.h>
#include <math.h>

#define B_SZ 256
#define R_SZ 2048
#define D_SZ 64
#define K_TOP 20
#define BLOCKS_PER_B 64          /* 32 rows per block */

// Candidate state. Zero-initialized at load; the finisher block re-zeros
// g_cnt/g_done after consuming them, so every launch/replay starts clean.
__device__ int                g_cnt[B_SZ];
__device__ int                g_done[B_SZ];
__device__ unsigned long long g_cand[B_SZ * R_SZ];
__device__ float              g_rinv[B_SZ * R_SZ];

__device__ __forceinline__ unsigned packf(float f) {
    unsigned u = __float_as_uint(f);
    return (u & 0x80000000u) ? ~u : (u | 0x80000000u);
}
__device__ __forceinline__ float unpackf(unsigned p) {
    unsigned b = (p & 0x80000000u) ? (p ^ 0x80000000u) : ~p;
    return __uint_as_float(b);
}

// ---------------------------------------------------------------------------
// Single fused kernel. Phase 1 (all blocks): stream-copy 32 rows + cosine
// sims + threshold filter (candidates published via L2 atomics). Phase 2
// (last arriving block per batch): top-k + weighting + query-row rewrite.
// ---------------------------------------------------------------------------
__global__ __launch_bounds__(256) void fused_kernel(
    const float* __restrict__ x,
    const int*   __restrict__ qrels,
    const float* __restrict__ thr_raw_p,
    const float* __restrict__ str_raw_p,
    const float* __restrict__ wscale_p,
    const float* __restrict__ temp_p,
    float*       __restrict__ out)
{
    const int tid  = threadIdx.x;
    const int wid  = tid >> 5;
    const int lane = tid & 31;
    const int half = lane >> 4;
    const int hl   = lane & 15;

    const int b = blockIdx.x >> 6;                     // 64 blocks per batch
    const long long base = (long long)blockIdx.x * 32 + wid * 4;
    const long long rowA = base + half * 2;
    const long long rowB = rowA + 1;
    const int qr = __ldg(&qrels[b]);

    // ---- phase 1: stream + sims ------------------------------------------
    const float4 vA = __ldcs(reinterpret_cast<const float4*>(x + rowA * D_SZ) + hl);
    const float4 vB = __ldcs(reinterpret_cast<const float4*>(x + rowB * D_SZ) + hl);
    const long long qrow = ((long long)b * R_SZ + qr) * D_SZ;
    const float4 q = __ldg(reinterpret_cast<const float4*>(x + qrow) + hl);

    __stcs(reinterpret_cast<float4*>(out + rowA * D_SZ) + hl, vA);
    __stcs(reinterpret_cast<float4*>(out + rowB * D_SZ) + hl, vB);

    float dotA = vA.x * q.x + vA.y * q.y + vA.z * q.z + vA.w * q.w;
    float ssA  = vA.x * vA.x + vA.y * vA.y + vA.z * vA.z + vA.w * vA.w;
    float dotB = vB.x * q.x + vB.y * q.y + vB.z * q.z + vB.w * q.w;
    float ssB  = vB.x * vB.x + vB.y * vB.y + vB.z * vB.z + vB.w * vB.w;
    float qs   = q.x * q.x + q.y * q.y + q.z * q.z + q.w * q.w;

    #pragma unroll
    for (int o = 8; o; o >>= 1) {       // stays within each 16-lane half
        dotA += __shfl_xor_sync(0xffffffffu, dotA, o);
        ssA  += __shfl_xor_sync(0xffffffffu, ssA,  o);
        dotB += __shfl_xor_sync(0xffffffffu, dotB, o);
        ssB  += __shfl_xor_sync(0xffffffffu, ssB,  o);
        qs   += __shfl_xor_sync(0xffffffffu, qs,   o);
    }

    if (hl == 0) {
        const float nqi = 1.0f / fmaxf(sqrtf(qs), 1e-12f);
        const float thr = 1.0f / (1.0f + expf(-__ldg(thr_raw_p)));
        const int rA = (int)(rowA & (R_SZ - 1));
        const int rB = rA + 1;

        const float nrA = fmaxf(sqrtf(ssA), 1e-12f);
        const float sA  = dotA * nqi / nrA;
        if (rA != qr && sA > thr) {
            const int pos = atomicAdd(&g_cnt[b], 1);
            const long long o = (long long)b * R_SZ + pos;
            atomicExch(&g_cand[o], ((unsigned long long)packf(sA) << 32)
                                   | (unsigned)(R_SZ - 1 - rA));
            atomicExch(&g_rinv[o], 1.0f / nrA);
        }
        const float nrB = fmaxf(sqrtf(ssB), 1e-12f);
        const float sB  = dotB * nqi / nrB;
        if (rB != qr && sB > thr) {
            const int pos = atomicAdd(&g_cnt[b], 1);
            const long long o = (long long)b * R_SZ + pos;
            atomicExch(&g_cand[o], ((unsigned long long)packf(sB) << 32)
                                   | (unsigned)(R_SZ - 1 - rB));
            atomicExch(&g_rinv[o], 1.0f / nrB);
        }
    }
    __syncthreads();

    // ---- arrival: last block of this batch becomes the finisher -----------
    __shared__ int s_finish;
    if (tid == 0) {
        __threadfence();                 // single release fence per block
        const int prev = atomicAdd(&g_done[b], 1);
        s_finish = (prev == BLOCKS_PER_B - 1);
    }
    __syncthreads();
    if (!s_finish) return;
    if (tid == 0) __threadfence();       // acquire side
    __syncthreads();

    // ---- phase 2: enhance for batch b --------------------------------------
    __shared__ float topv[K_TOP];
    __shared__ int   topi[K_TOP];
    __shared__ int   spos[K_TOP];
    __shared__ float srin[K_TOP];
    __shared__ float adj[K_TOP];
    __shared__ float s_strength;
    __shared__ int   s_nsel;

    const unsigned long long* cb = g_cand + (long long)b * R_SZ;

    if (tid < 32) {
        int c = 0;
        if (lane == 0) { c = g_cnt[b]; g_cnt[b] = 0; g_done[b] = 0; }
        unsigned long long k0 = __ldcg(cb + lane);
        unsigned long long k1 = __ldcg(cb + lane + 32);
        unsigned long long k2 = __ldcg(cb + lane + 64);
        unsigned long long k3 = __ldcg(cb + lane + 96);
        const int ncand = min(__shfl_sync(0xffffffffu, c, 0), R_SZ - 1);
        const int nsel  = min(ncand, K_TOP);
        if (lane == 0) s_nsel = nsel;

        if ((lane)      >= ncand) k0 = 0ull;
        if ((lane + 32) >= ncand) k1 = 0ull;
        if ((lane + 64) >= ncand) k2 = 0ull;
        if ((lane + 96) >= ncand) k3 = 0ull;

        unsigned long long prevk = ~0ull;
        for (int it = 0; it < nsel; ++it) {
            unsigned long long lb = 0ull; int lp = -1;
            if (k0 < prevk && k0 > lb) { lb = k0; lp = lane; }
            if (k1 < prevk && k1 > lb) { lb = k1; lp = lane + 32; }
            if (k2 < prevk && k2 > lb) { lb = k2; lp = lane + 64; }
            if (k3 < prevk && k3 > lb) { lb = k3; lp = lane + 96; }
            for (int j = 128 + lane; j < ncand; j += 32) {   // cold path
                unsigned long long k = __ldcg(cb + j);
                if (k < prevk && k > lb) { lb = k; lp = j; }
            }
            #pragma unroll
            for (int o = 16; o; o >>= 1) {
                unsigned long long ok = __shfl_xor_sync(0xffffffffu, lb, o);
                int op = __shfl_xor_sync(0xffffffffu, lp, o);
                if (ok > lb) { lb = ok; lp = op; }
            }
            prevk = lb;
            if (lane == 0) {
                topi[it] = (R_SZ - 1) - (int)(lb & 0xffffffffu);
                topv[it] = unpackf((unsigned)(lb >> 32));
                spos[it] = lp;
            }
        }
    }
    __syncthreads();

    const int nsel = s_nsel;
    if (tid < nsel) srin[tid] = __ldcg(g_rinv + (long long)b * R_SZ + spos[tid]);

    if (tid == 0) {
        const float thr      = 1.0f / (1.0f + expf(-thr_raw_p[0]));
        const float strength = 0.2f / (1.0f + expf(-str_raw_p[0]));
        const float tempv    = fminf(fmaxf(temp_p[0], 0.1f), 10.0f);
        const float ws       = wscale_p[0];

        float m = -1e9f;
        for (int k = 0; k < nsel; ++k) m = fmaxf(m, topv[k] / tempv);
        float se = 0.0f;
        float ev[K_TOP];
        for (int k = 0; k < nsel; ++k) { ev[k] = expf(topv[k] / tempv - m); se += ev[k]; }

        float suma = 0.0f;
        for (int k = 0; k < nsel; ++k) {
            const float wgt = ev[k] / se;
            const float sw  = 1.0f / (1.0f + expf(-(topv[k] - thr) * 10.0f));
            const float a   = wgt * sw * (1.0f + ws * topv[k]);
            adj[k] = a;
            suma  += a;
        }
        const float inv = 1.0f / (suma + 1e-8f);
        for (int k = 0; k < nsel; ++k) adj[k] *= inv;
        s_strength = strength;
    }
    __syncthreads();

    if (tid < D_SZ) {
        const long long qoff = ((long long)b * R_SZ + qr) * D_SZ;
        const float qo = x[qoff + tid];
        float acc = 0.0f;
        for (int k = 0; k < nsel; ++k)
            acc += (adj[k] * srin[k]) * x[((long long)b * R_SZ + topi[k]) * D_SZ + tid];
        const float s = s_strength;
        out[qoff + tid] = (nsel > 0) ? (1.0f - s) * qo + s * acc : qo;
    }
}

// ---------------------------------------------------------------------------
extern "C" void kernel_launch(void* const* d_in, const int* in_sizes, int n_in,
                              void* d_out, int out_size)
{
    const float* x     = (const float*)d_in[0];
    const int*   qrels = (const int*)  d_in[1];
    const float* thr   = (const float*)d_in[2];
    const float* str   = (const float*)d_in[3];
    const float* wsc   = (const float*)d_in[4];
    const float* tmp   = (const float*)d_in[5];
    float* out = (float*)d_out;

    const int blocks = B_SZ * BLOCKS_PER_B;              // 16384
    fused_kernel<<<blocks, 256>>>(x, qrels, thr, str, wsc, tmp, out);
}

// round 13
// speedup vs baseline: 1.0273x; 1.0165x over previous
#include <cuda_runtime.h>
#include <cuda_bf16.h>
#include <math.h>

#define B_SZ 256
#define R_SZ 2048
#define D_SZ 64
#define K_TOP 20
#define BLOCKS_PER_B 64          /* 32 rows per block */

// Candidate state. Zero-initialized at load; the finisher block re-zeros
// g_cnt/g_done after consuming them, so every launch/replay starts clean.
__device__ int                g_cnt[B_SZ];
__device__ int                g_done[B_SZ];
__device__ unsigned long long g_cand[B_SZ * R_SZ];
__device__ float              g_rinv[B_SZ * R_SZ];

__device__ __forceinline__ unsigned packf(float f) {
    unsigned u = __float_as_uint(f);
    return (u & 0x80000000u) ? ~u : (u | 0x80000000u);
}
__device__ __forceinline__ float unpackf(unsigned p) {
    unsigned b = (p & 0x80000000u) ? (p ^ 0x80000000u) : ~p;
    return __uint_as_float(b);
}

// ---------------------------------------------------------------------------
// Single fused kernel. Phase 1 (all blocks): stream-copy 32 rows + cosine
// sims + threshold filter (candidates published via L2 atomics). Phase 2
// (last arriving block per batch): top-k + weighting + query-row rewrite.
// ---------------------------------------------------------------------------
__global__ __launch_bounds__(256) void fused_kernel(
    const float* __restrict__ x,
    const int*   __restrict__ qrels,
    const float* __restrict__ thr_raw_p,
    const float* __restrict__ str_raw_p,
    const float* __restrict__ wscale_p,
    const float* __restrict__ temp_p,
    float*       __restrict__ out)
{
    const int tid  = threadIdx.x;
    const int wid  = tid >> 5;
    const int lane = tid & 31;
    const int half = lane >> 4;
    const int hl   = lane & 15;

    const int b = blockIdx.x >> 6;                     // 64 blocks per batch
    const long long base = (long long)blockIdx.x * 32 + wid * 4;
    const long long rowA = base + half * 2;
    const long long rowB = rowA + 1;
    const int qr = __ldg(&qrels[b]);

    // ---- phase 1: stream + sims ------------------------------------------
    const float4 vA = __ldcs(reinterpret_cast<const float4*>(x + rowA * D_SZ) + hl);
    const float4 vB = __ldcs(reinterpret_cast<const float4*>(x + rowB * D_SZ) + hl);
    const long long qrow = ((long long)b * R_SZ + qr) * D_SZ;
    const float4 q = __ldg(reinterpret_cast<const float4*>(x + qrow) + hl);

    __stcs(reinterpret_cast<float4*>(out + rowA * D_SZ) + hl, vA);
    __stcs(reinterpret_cast<float4*>(out + rowB * D_SZ) + hl, vB);

    float dotA = vA.x * q.x + vA.y * q.y + vA.z * q.z + vA.w * q.w;
    float ssA  = vA.x * vA.x + vA.y * vA.y + vA.z * vA.z + vA.w * vA.w;
    float dotB = vB.x * q.x + vB.y * q.y + vB.z * q.z + vB.w * q.w;
    float ssB  = vB.x * vB.x + vB.y * vB.y + vB.z * vB.z + vB.w * vB.w;
    float qs   = q.x * q.x + q.y * q.y + q.z * q.z + q.w * q.w;

    #pragma unroll
    for (int o = 8; o; o >>= 1) {       // stays within each 16-lane half
        dotA += __shfl_xor_sync(0xffffffffu, dotA, o);
        ssA  += __shfl_xor_sync(0xffffffffu, ssA,  o);
        dotB += __shfl_xor_sync(0xffffffffu, dotB, o);
        ssB  += __shfl_xor_sync(0xffffffffu, ssB,  o);
        qs   += __shfl_xor_sync(0xffffffffu, qs,   o);
    }

    if (hl == 0) {
        const float nqi = 1.0f / fmaxf(sqrtf(qs), 1e-12f);
        const float thr = 1.0f / (1.0f + expf(-__ldg(thr_raw_p)));
        const int rA = (int)(rowA & (R_SZ - 1));
        const int rB = rA + 1;

        const float nrA = fmaxf(sqrtf(ssA), 1e-12f);
        const float sA  = dotA * nqi / nrA;
        if (rA != qr && sA > thr) {
            const int pos = atomicAdd(&g_cnt[b], 1);
            const long long o = (long long)b * R_SZ + pos;
            atomicExch(&g_cand[o], ((unsigned long long)packf(sA) << 32)
                                   | (unsigned)(R_SZ - 1 - rA));
            atomicExch(&g_rinv[o], 1.0f / nrA);
        }
        const float nrB = fmaxf(sqrtf(ssB), 1e-12f);
        const float sB  = dotB * nqi / nrB;
        if (rB != qr && sB > thr) {
            const int pos = atomicAdd(&g_cnt[b], 1);
            const long long o = (long long)b * R_SZ + pos;
            atomicExch(&g_cand[o], ((unsigned long long)packf(sB) << 32)
                                   | (unsigned)(R_SZ - 1 - rB));
            atomicExch(&g_rinv[o], 1.0f / nrB);
        }
    }
    __syncthreads();

    // ---- arrival: last block of this batch becomes the finisher -----------
    __shared__ int s_finish;
    if (tid == 0) {
        __threadfence();                 // single release fence per block
        const int prev = atomicAdd(&g_done[b], 1);
        s_finish = (prev == BLOCKS_PER_B - 1);
    }
    __syncthreads();
    if (!s_finish) return;
    if (tid == 0) __threadfence();       // acquire side
    __syncthreads();

    // ---- phase 2: enhance for batch b --------------------------------------
    __shared__ float topv[K_TOP];
    __shared__ int   topi[K_TOP];
    __shared__ int   spos[K_TOP];
    __shared__ float srin[K_TOP];
    __shared__ float adj[K_TOP];
    __shared__ float s_strength;
    __shared__ int   s_nsel;

    const unsigned long long* cb = g_cand + (long long)b * R_SZ;

    if (tid < 32) {
        int c = 0;
        if (lane == 0) { c = g_cnt[b]; g_cnt[b] = 0; g_done[b] = 0; }
        unsigned long long k0 = __ldcg(cb + lane);
        unsigned long long k1 = __ldcg(cb + lane + 32);
        unsigned long long k2 = __ldcg(cb + lane + 64);
        unsigned long long k3 = __ldcg(cb + lane + 96);
        const int ncand = min(__shfl_sync(0xffffffffu, c, 0), R_SZ - 1);
        const int nsel  = min(ncand, K_TOP);
        if (lane == 0) s_nsel = nsel;

        if ((lane)      >= ncand) k0 = 0ull;
        if ((lane + 32) >= ncand) k1 = 0ull;
        if ((lane + 64) >= ncand) k2 = 0ull;
        if ((lane + 96) >= ncand) k3 = 0ull;

        unsigned long long prevk = ~0ull;
        for (int it = 0; it < nsel; ++it) {
            unsigned long long lb = 0ull; int lp = -1;
            if (k0 < prevk && k0 > lb) { lb = k0; lp = lane; }
            if (k1 < prevk && k1 > lb) { lb = k1; lp = lane + 32; }
            if (k2 < prevk && k2 > lb) { lb = k2; lp = lane + 64; }
            if (k3 < prevk && k3 > lb) { lb = k3; lp = lane + 96; }
            for (int j = 128 + lane; j < ncand; j += 32) {   // cold path
                unsigned long long k = __ldcg(cb + j);
                if (k < prevk && k > lb) { lb = k; lp = j; }
            }
            #pragma unroll
            for (int o = 16; o; o >>= 1) {
                unsigned long long ok = __shfl_xor_sync(0xffffffffu, lb, o);
                int op = __shfl_xor_sync(0xffffffffu, lp, o);
                if (ok > lb) { lb = ok; lp = op; }
            }
            prevk = lb;
            if (lane == 0) {
                topi[it] = (R_SZ - 1) - (int)(lb & 0xffffffffu);
                topv[it] = unpackf((unsigned)(lb >> 32));
                spos[it] = lp;
            }
        }
    }
    __syncthreads();

    const int nsel = s_nsel;
    if (tid < nsel) srin[tid] = __ldcg(g_rinv + (long long)b * R_SZ + spos[tid]);

    if (tid == 0) {
        const float thr      = 1.0f / (1.0f + expf(-thr_raw_p[0]));
        const float strength = 0.2f / (1.0f + expf(-str_raw_p[0]));
        const float tempv    = fminf(fmaxf(temp_p[0], 0.1f), 10.0f);
        const float ws       = wscale_p[0];

        float m = -1e9f;
        for (int k = 0; k < nsel; ++k) m = fmaxf(m, topv[k] / tempv);
        float se = 0.0f;
        float ev[K_TOP];
        for (int k = 0; k < nsel; ++k) { ev[k] = expf(topv[k] / tempv - m); se += ev[k]; }

        float suma = 0.0f;
        for (int k = 0; k < nsel; ++k) {
            const float wgt = ev[k] / se;
            const float sw  = 1.0f / (1.0f + expf(-(topv[k] - thr) * 10.0f));
            const float a   = wgt * sw * (1.0f + ws * topv[k]);
            adj[k] = a;
            suma  += a;
        }
        const float inv = 1.0f / (suma + 1e-8f);
        for (int k = 0; k < nsel; ++k) adj[k] *= inv;
        s_strength = strength;
    }
    __syncthreads();

    if (tid < D_SZ) {
        const long long qoff = ((long long)b * R_SZ + qr) * D_SZ;
        const float qo = x[qoff + tid];
        float acc = 0.0f;
        for (int k = 0; k < nsel; ++k)
            acc += (adj[k] * srin[k]) * x[((long long)b * R_SZ + topi[k]) * D_SZ + tid];
        const float s = s_strength;
        out[qoff + tid] = (nsel > 0) ? (1.0f - s) * qo + s * acc : qo;
    }
}

// ---------------------------------------------------------------------------
extern "C" void kernel_launch(void* const* d_in, const int* in_sizes, int n_in,
                              void* d_out, int out_size)
{
    const float* x     = (const float*)d_in[0];
    const int*   qrels = (const int*)  d_in[1];
    const float* thr   = (const float*)d_in[2];
    const float* str   = (const float*)d_in[3];
    const float* wsc   = (const float*)d_in[4];
    const float* tmp   = (const float*)d_in[5];
    float* out = (float*)d_out;

    const int blocks = B_SZ * BLOCKS_PER_B;              // 16384
    fused_kernel<<<blocks, 256>>>(x, qrels, thr, str, wsc, tmp, out);
}